// round 7
// baseline (speedup 1.0000x reference)
#include <cuda_runtime.h>
#include <cuda_fp16.h>
#include <math.h>
#include <stdint.h>

#define L_SEQ 2048
#define DM    1024
#define DI    2048
#define DS    16
#define DTR   64
#define XDBL  96
#define NCH   8
#define CL    (L_SEQ / NCH)   // 256

// float scratch
__device__ float g_xz[L_SEQ * 2 * DI];
__device__ float g_xs[L_SEQ * DI];
__device__ float g_xdbl[L_SEQ * XDBL];
__device__ float g_dt[L_SEQ * DI];
// chunked-scan scratch
__device__ float g_P[NCH * DI * DS];
__device__ float g_q[NCH * DI * DS];
__device__ float g_hin[NCH * DI * DS];
// half scratch
__device__ __half g_xh[L_SEQ * DM];
__device__ __half g_Winh[2 * DI * DM];
__device__ __half g_Wxh[XDBL * DI];
__device__ __half g_Wdth[DI * DTR];
__device__ __half g_Wouth[DM * DI];
__device__ __half g_xsh[L_SEQ * DI];
__device__ __half g_xdblh[L_SEQ * XDBL];
__device__ __half g_yh[L_SEQ * DI];

// ---------------------------------------------------------------------------
__device__ __forceinline__ void cpasync16(void* smem_ptr, const void* gptr) {
    uint32_t sa = (uint32_t)__cvta_generic_to_shared(smem_ptr);
    asm volatile("cp.async.cg.shared.global [%0], [%1], 16;" :: "r"(sa), "l"(gptr));
}
__device__ __forceinline__ void mma_f16(float* d, const uint32_t* a, const uint32_t* b) {
    asm volatile(
        "mma.sync.aligned.m16n8k16.row.col.f32.f16.f16.f32 "
        "{%0,%1,%2,%3}, {%4,%5,%6,%7}, {%8,%9}, {%0,%1,%2,%3};"
        : "+f"(d[0]), "+f"(d[1]), "+f"(d[2]), "+f"(d[3])
        : "r"(a[0]), "r"(a[1]), "r"(a[2]), "r"(a[3]), "r"(b[0]), "r"(b[1]));
}
__device__ __forceinline__ void ldsm_x4(uint32_t& r0, uint32_t& r1,
                                        uint32_t& r2, uint32_t& r3, uint32_t addr) {
    asm volatile("ldmatrix.sync.aligned.m8n8.x4.shared.b16 {%0,%1,%2,%3}, [%4];"
                 : "=r"(r0), "=r"(r1), "=r"(r2), "=r"(r3) : "r"(addr));
}

// ---------------------------------------------------------------------------
// float -> half converters
// ---------------------------------------------------------------------------
__device__ __forceinline__ void f2h4(const float4* s, uint2* d, int i) {
    float4 v = s[i];
    __half2 h0 = __floats2half2_rn(v.x, v.y);
    __half2 h1 = __floats2half2_rn(v.z, v.w);
    d[i] = make_uint2(*(uint32_t*)&h0, *(uint32_t*)&h1);
}
__global__ void f2h_kernel(const float4* __restrict__ src, uint2* __restrict__ dst, int n4)
{
    int i = blockIdx.x * blockDim.x + threadIdx.x;
    if (i < n4) f2h4(src, dst, i);
}
__global__ void f2h3_kernel(const float4* s0, uint2* d0, int n0,
                            const float4* s1, uint2* d1, int n1,
                            const float4* s2, uint2* d2, int n2)
{
    int i = blockIdx.x * blockDim.x + threadIdx.x;
    int stride = gridDim.x * blockDim.x;
    for (int j = i; j < n0; j += stride) f2h4(s0, d0, j);
    for (int j = i; j < n1; j += stride) f2h4(s1, d1, j);
    for (int j = i; j < n2; j += stride) f2h4(s2, d2, j);
}

// ---------------------------------------------------------------------------
// fp16 tensor-core GEMM, ldmatrix fragments, template BN (128 or 256).
// CTA 128xBN, BK=32, 8 warps. BN=128: warps 64x32; BN=256: warps 64x64.
// M%128==0, K%32==0; N tail allowed for BN=128 only (zero-filled B rows).
// Dynamic smem.
// ---------------------------------------------------------------------------
#define LDH 40

template<int BN, bool SOFTPLUS, bool WRITE_HALF>
__global__ void __launch_bounds__(256, 1) gemm_h(
    const __half* __restrict__ A, const __half* __restrict__ B,
    const float* __restrict__ bias, float* __restrict__ C,
    __half* __restrict__ Ch,
    int M, int N, int K, int lda, int ldb, int ldc)
{
    constexpr int NI = BN / 32;          // mma n-tiles per warp (4 or 8)
    extern __shared__ __half sm[];
    __half (*As)[128][LDH] = (__half(*)[128][LDH])sm;
    __half (*Bs)[BN][LDH]  = (__half(*)[BN][LDH])(sm + 2 * 128 * LDH);

    const int tid  = threadIdx.x;
    const int wid  = tid >> 5, lane = tid & 31;
    const int g    = lane >> 2, tg = lane & 3;
    const int wm   = (wid >> 2) * 64;
    const int wn   = (wid & 3) * (BN / 4);
    const int m0   = blockIdx.y * 128, n0 = blockIdx.x * BN;

    const int lm_row = (lane & 7) + ((lane >> 3) & 1) * 8;
    const int lm_col = (lane >> 4) * 8;
    const uint32_t lm_off = (uint32_t)(lm_row * LDH + lm_col) * 2;
    const uint32_t as_base = (uint32_t)__cvta_generic_to_shared(&As[0][0][0]);
    const uint32_t bs_base = (uint32_t)__cvta_generic_to_shared(&Bs[0][0][0]);
    const uint32_t a_tile_bytes = 128 * LDH * 2;
    const uint32_t b_tile_bytes = BN * LDH * 2;

    if (BN == 128 && n0 + BN > N) {
        int rstart = N - n0; if (rstart < 0) rstart = 0;
        for (int i = tid; i < 2 * BN * (LDH / 2); i += 256) {
            int r = (i / (LDH / 2)) % BN;
            if (r >= rstart) ((uint32_t*)&Bs[0][0][0])[i] = 0u;
        }
        __syncthreads();
    }

    const int KT = K / 32;

    auto load_tiles = [&](int kt, int buf) {
        const __half* Ab = A + (size_t)m0 * lda + kt * 32;
        const __half* Bb = B + (size_t)n0 * ldb + kt * 32;
#pragma unroll
        for (int i = 0; i < 2; ++i) {            // A: 512 cps
            int f = tid + i * 256;
            int r = f >> 2, c = (f & 3) * 8;
            cpasync16(&As[buf][r][c], Ab + (size_t)r * lda + c);
        }
#pragma unroll
        for (int i = 0; i < BN / 64; ++i) {       // B: BN*4 cps
            int f = tid + i * 256;
            int r = f >> 2, c = (f & 3) * 8;
            if (BN == 256 || n0 + r < N)
                cpasync16(&Bs[buf][r][c], Bb + (size_t)r * ldb + c);
        }
    };

    float acc[4][NI][4];
#pragma unroll
    for (int i = 0; i < 4; ++i)
#pragma unroll
        for (int j = 0; j < NI; ++j)
#pragma unroll
            for (int r = 0; r < 4; ++r) acc[i][j][r] = 0.f;

    load_tiles(0, 0);
    asm volatile("cp.async.commit_group;");

    for (int kt = 0; kt < KT; ++kt) {
        if (kt + 1 < KT) {
            load_tiles(kt + 1, (kt + 1) & 1);
            asm volatile("cp.async.commit_group;");
            asm volatile("cp.async.wait_group 1;");
        } else {
            asm volatile("cp.async.wait_group 0;");
        }
        __syncthreads();

        const int buf = kt & 1;
        const uint32_t abuf = as_base + buf * a_tile_bytes + lm_off;
        const uint32_t bbuf = bs_base + buf * b_tile_bytes + lm_off;
#pragma unroll
        for (int ks = 0; ks < 2; ++ks) {
            const uint32_t k0b = (uint32_t)(ks * 16) * 2;
            uint32_t af[4][4], bf[NI][2];
#pragma unroll
            for (int mi = 0; mi < 4; ++mi)
                ldsm_x4(af[mi][0], af[mi][1], af[mi][2], af[mi][3],
                        abuf + (uint32_t)((wm + mi * 16) * LDH) * 2 + k0b);
#pragma unroll
            for (int p = 0; p < NI / 2; ++p)
                ldsm_x4(bf[2 * p][0], bf[2 * p + 1][0], bf[2 * p][1], bf[2 * p + 1][1],
                        bbuf + (uint32_t)((wn + p * 16) * LDH) * 2 + k0b);
#pragma unroll
            for (int mi = 0; mi < 4; ++mi)
#pragma unroll
                for (int ni = 0; ni < NI; ++ni)
                    mma_f16(acc[mi][ni], af[mi], bf[ni]);
        }
        __syncthreads();
    }

    // epilogue
#pragma unroll
    for (int mi = 0; mi < 4; ++mi) {
        const int r0 = m0 + wm + mi * 16 + g;
#pragma unroll
        for (int ni = 0; ni < NI; ++ni) {
            const int col = n0 + wn + ni * 8 + 2 * tg;
            if (BN == 128 && col >= N) continue;
            float v0 = acc[mi][ni][0], v1 = acc[mi][ni][1];
            float v2 = acc[mi][ni][2], v3 = acc[mi][ni][3];
            if (SOFTPLUS) {
                float b0 = bias[col], b1 = bias[col + 1];
                v0 += b0; v1 += b1; v2 += b0; v3 += b1;
                v0 = (v0 > 20.f) ? v0 : log1pf(expf(v0));
                v1 = (v1 > 20.f) ? v1 : log1pf(expf(v1));
                v2 = (v2 > 20.f) ? v2 : log1pf(expf(v2));
                v3 = (v3 > 20.f) ? v3 : log1pf(expf(v3));
            }
            *(float2*)&C[(size_t)r0 * ldc + col]       = make_float2(v0, v1);
            *(float2*)&C[(size_t)(r0 + 8) * ldc + col] = make_float2(v2, v3);
            if (WRITE_HALF) {
                *(__half2*)&Ch[(size_t)r0 * ldc + col]       = __floats2half2_rn(v0, v1);
                *(__half2*)&Ch[(size_t)(r0 + 8) * ldc + col] = __floats2half2_rn(v2, v3);
            }
        }
    }
}

// ---------------------------------------------------------------------------
// Depthwise causal conv (4-tap) + SiLU -> float (scan) + half (GEMM)
// ---------------------------------------------------------------------------
__global__ void conv_silu_kernel(const float* __restrict__ cw,
                                 const float* __restrict__ cb)
{
    int idx = blockIdx.x * blockDim.x + threadIdx.x;
    if (idx >= L_SEQ * DI) return;
    int l = idx / DI, d = idx % DI;
    float acc = cb[d];
#pragma unroll
    for (int t = 0; t < 4; ++t) {
        int ll = l - 3 + t;
        if (ll >= 0) acc = fmaf(cw[d * 4 + t], g_xz[(size_t)ll * (2 * DI) + d], acc);
    }
    float s = acc / (1.f + __expf(-acc));
    g_xs[idx]  = s;
    g_xsh[idx] = __float2half_rn(s);
}

// ---------------------------------------------------------------------------
// Chunked selective scan (3 passes)
// ---------------------------------------------------------------------------
#define PF 8
__global__ void __launch_bounds__(256) scan_part1(const float* __restrict__ A_log)
{
    const int d = blockIdx.x * 16 + (threadIdx.x >> 4);
    const int n = threadIdx.x & 15;
    const int c = blockIdx.y;
    const float a = -__expf(A_log[d * DS + n]);
    const int lbase = c * CL;

    float cdt[PF], cxv[PF], cb[PF];
#pragma unroll
    for (int j = 0; j < PF; ++j) {
        int l = lbase + j;
        cdt[j] = g_dt[(size_t)l * DI + d];
        cxv[j] = g_xs[(size_t)l * DI + d];
        cb[j]  = g_xdbl[l * XDBL + DTR + n];
    }

    float h = 0.f, P = 1.f;
    for (int l0 = 0; l0 < CL; l0 += PF) {
        float ndt[PF], nxv[PF], nb[PF];
        const bool more = (l0 + PF < CL);
        if (more) {
#pragma unroll
            for (int j = 0; j < PF; ++j) {
                int l = lbase + l0 + PF + j;
                ndt[j] = g_dt[(size_t)l * DI + d];
                nxv[j] = g_xs[(size_t)l * DI + d];
                nb[j]  = g_xdbl[l * XDBL + DTR + n];
            }
        }
#pragma unroll
        for (int j = 0; j < PF; ++j) {
            float dA = __expf(cdt[j] * a);
            h = fmaf(dA, h, cdt[j] * cb[j] * cxv[j]);
            P *= dA;
        }
        if (more) {
#pragma unroll
            for (int j = 0; j < PF; ++j) { cdt[j] = ndt[j]; cxv[j] = nxv[j]; cb[j] = nb[j]; }
        }
    }
    g_q[((size_t)c * DI + d) * DS + n] = h;
    g_P[((size_t)c * DI + d) * DS + n] = P;
}

__global__ void __launch_bounds__(256) scan_combine()
{
    int idx = blockIdx.x * blockDim.x + threadIdx.x;
    if (idx >= DI * DS) return;
    float hin = 0.f;
    g_hin[idx] = 0.f;
#pragma unroll
    for (int c = 0; c < NCH - 1; ++c) {
        hin = fmaf(g_P[(size_t)c * DI * DS + idx], hin, g_q[(size_t)c * DI * DS + idx]);
        g_hin[(size_t)(c + 1) * DI * DS + idx] = hin;
    }
}

__global__ void __launch_bounds__(256) scan_part2(
    const float* __restrict__ A_log, const float* __restrict__ Dp)
{
    const int d = blockIdx.x * 16 + (threadIdx.x >> 4);
    const int n = threadIdx.x & 15;
    const int c = blockIdx.y;
    const float a  = -__expf(A_log[d * DS + n]);
    const float Dd = Dp[d];
    const bool lead = (n == 0);
    const int lbase = c * CL;

    float cdt[PF], cxv[PF], cb[PF], cc[PF], cz[PF];
#pragma unroll
    for (int j = 0; j < PF; ++j) {
        int l = lbase + j;
        cdt[j] = g_dt[(size_t)l * DI + d];
        cxv[j] = g_xs[(size_t)l * DI + d];
        cb[j]  = g_xdbl[l * XDBL + DTR + n];
        cc[j]  = g_xdbl[l * XDBL + DTR + DS + n];
        cz[j]  = lead ? g_xz[(size_t)l * (2 * DI) + DI + d] : 0.f;
    }

    float h = g_hin[((size_t)c * DI + d) * DS + n];
    for (int l0 = 0; l0 < CL; l0 += PF) {
        float ndt[PF], nxv[PF], nb[PF], nc[PF], nz[PF];
        const bool more = (l0 + PF < CL);
        if (more) {
#pragma unroll
            for (int j = 0; j < PF; ++j) {
                int l = lbase + l0 + PF + j;
                ndt[j] = g_dt[(size_t)l * DI + d];
                nxv[j] = g_xs[(size_t)l * DI + d];
                nb[j]  = g_xdbl[l * XDBL + DTR + n];
                nc[j]  = g_xdbl[l * XDBL + DTR + DS + n];
                nz[j]  = lead ? g_xz[(size_t)l * (2 * DI) + DI + d] : 0.f;
            }
        }
#pragma unroll
        for (int j = 0; j < PF; ++j) {
            float dt = cdt[j], xv = cxv[j];
            float dA = __expf(dt * a);
            h = fmaf(dA, h, dt * cb[j] * xv);
            float p = h * cc[j];
            p += __shfl_xor_sync(0xffffffffu, p, 1);
            p += __shfl_xor_sync(0xffffffffu, p, 2);
            p += __shfl_xor_sync(0xffffffffu, p, 4);
            p += __shfl_xor_sync(0xffffffffu, p, 8);
            if (lead) {
                float z  = cz[j];
                float sz = z / (1.f + __expf(-z));
                g_yh[(size_t)(lbase + l0 + j) * DI + d] =
                    __float2half_rn((p + xv * Dd) * sz);
            }
        }
        if (more) {
#pragma unroll
            for (int j = 0; j < PF; ++j) {
                cdt[j] = ndt[j]; cxv[j] = nxv[j];
                cb[j] = nb[j]; cc[j] = nc[j]; cz[j] = nz[j];
            }
        }
    }
}

// ---------------------------------------------------------------------------
extern "C" void kernel_launch(void* const* d_in, const int* in_sizes, int n_in,
                              void* d_out, int out_size)
{
    const float* x     = (const float*)d_in[0];
    const float* W_in  = (const float*)d_in[1];
    const float* cw    = (const float*)d_in[2];
    const float* cb    = (const float*)d_in[3];
    const float* W_x   = (const float*)d_in[4];
    const float* W_dt  = (const float*)d_in[5];
    const float* b_dt  = (const float*)d_in[6];
    const float* A_log = (const float*)d_in[7];
    const float* Dp    = (const float*)d_in[8];
    const float* W_out = (const float*)d_in[9];
    float* out = (float*)d_out;

    float *xz, *xdbl, *dt;
    __half *xh, *Winh, *Wxh, *Wdth, *Wouth, *xsh, *xdblh, *yh;
    cudaGetSymbolAddress((void**)&xz,    g_xz);
    cudaGetSymbolAddress((void**)&xdbl,  g_xdbl);
    cudaGetSymbolAddress((void**)&dt,    g_dt);
    cudaGetSymbolAddress((void**)&xh,    g_xh);
    cudaGetSymbolAddress((void**)&Winh,  g_Winh);
    cudaGetSymbolAddress((void**)&Wxh,   g_Wxh);
    cudaGetSymbolAddress((void**)&Wdth,  g_Wdth);
    cudaGetSymbolAddress((void**)&Wouth, g_Wouth);
    cudaGetSymbolAddress((void**)&xsh,   g_xsh);
    cudaGetSymbolAddress((void**)&xdblh, g_xdblh);
    cudaGetSymbolAddress((void**)&yh,    g_yh);

    const int SM128 = (2 * 128 * LDH + 2 * 128 * LDH) * 2;  // 40960 B
    const int SM256 = (2 * 128 * LDH + 2 * 256 * LDH) * 2;  // 61440 B
    cudaFuncSetAttribute(gemm_h<256, false, false>,
        cudaFuncAttributeMaxDynamicSharedMemorySize, SM256);
    cudaFuncSetAttribute(gemm_h<256, true, false>,
        cudaFuncAttributeMaxDynamicSharedMemorySize, SM256);
    cudaFuncSetAttribute(gemm_h<128, false, false>,
        cudaFuncAttributeMaxDynamicSharedMemorySize, SM128);
    cudaFuncSetAttribute(gemm_h<128, false, true>,
        cudaFuncAttributeMaxDynamicSharedMemorySize, SM128);

    // 0) f2h: 3 launches (keeps gemm1 at capture slot #4)
    const int CT = 256;
    f2h_kernel<<<(L_SEQ * DM / 4 + CT - 1) / CT, CT>>>((const float4*)x, (uint2*)xh, L_SEQ * DM / 4);
    f2h_kernel<<<(2 * DI * DM / 4 + CT - 1) / CT, CT>>>((const float4*)W_in, (uint2*)Winh, 2 * DI * DM / 4);
    f2h3_kernel<<<592, CT>>>((const float4*)W_x, (uint2*)Wxh, XDBL * DI / 4,
                             (const float4*)W_dt, (uint2*)Wdth, DI * DTR / 4,
                             (const float4*)W_out, (uint2*)Wouth, DM * DI / 4);

    // 1) xz = x @ W_in^T : BN=256, grid 16x16
    gemm_h<256, false, false><<<dim3(4096 / 256, 2048 / 128), 256, SM256>>>(
        xh, Winh, nullptr, xz, nullptr, L_SEQ, 2 * DI, DM, DM, DM, 2 * DI);

    // 2) conv + silu
    conv_silu_kernel<<<(L_SEQ * DI + 255) / 256, 256>>>(cw, cb);

    // 3) x_dbl = xs @ W_x^T (N=96 tail) : BN=128
    gemm_h<128, false, true><<<dim3(1, 2048 / 128), 256, SM128>>>(
        xsh, Wxh, nullptr, xdbl, xdblh, L_SEQ, XDBL, DI, DI, DI, XDBL);

    // 4) dt = softplus(...) : BN=256, grid 8x16
    gemm_h<256, true, false><<<dim3(2048 / 256, 2048 / 128), 256, SM256>>>(
        xdblh, Wdth, b_dt, dt, nullptr, L_SEQ, DI, DTR, XDBL, DTR, DI);

    // 5) chunked selective scan
    scan_part1<<<dim3(DI / 16, NCH - 1), 256>>>(A_log);
    scan_combine<<<(DI * DS + 255) / 256, 256>>>();
    scan_part2<<<dim3(DI / 16, NCH), 256>>>(A_log, Dp);

    // 6) out = y @ W_out^T : BN=128, grid 8x16
    gemm_h<128, false, false><<<dim3(1024 / 128, 2048 / 128), 256, SM128>>>(
        yh, Wouth, nullptr, out, nullptr, L_SEQ, DM, DI, DI, DI, DM);
}

// round 8
// speedup vs baseline: 1.1358x; 1.1358x over previous
#include <cuda_runtime.h>
#include <cuda_fp16.h>
#include <math.h>
#include <stdint.h>

#define L_SEQ 2048
#define DM    1024
#define DI    2048
#define DS    16
#define DTR   64
#define XDBL  96
#define NCH   8
#define CL    (L_SEQ / NCH)   // 256

// float scratch
__device__ float g_xz[L_SEQ * 2 * DI];
__device__ float g_xs[L_SEQ * DI];
__device__ float g_xdbl[L_SEQ * XDBL];
__device__ float g_dt[L_SEQ * DI];
// split-K partial slabs
__device__ float g_part_xdbl[8 * L_SEQ * XDBL];
__device__ float g_part_out[2 * L_SEQ * DM];
// chunked-scan scratch
__device__ float g_P[NCH * DI * DS];
__device__ float g_q[NCH * DI * DS];
__device__ float g_hin[NCH * DI * DS];
// half scratch
__device__ __half g_xh[L_SEQ * DM];
__device__ __half g_Winh[2 * DI * DM];
__device__ __half g_Wxh[XDBL * DI];
__device__ __half g_Wdth[DI * DTR];
__device__ __half g_Wouth[DM * DI];
__device__ __half g_xsh[L_SEQ * DI];
__device__ __half g_xdblh[L_SEQ * XDBL];
__device__ __half g_yh[L_SEQ * DI];

// ---------------------------------------------------------------------------
__device__ __forceinline__ void cpasync16(void* smem_ptr, const void* gptr) {
    uint32_t sa = (uint32_t)__cvta_generic_to_shared(smem_ptr);
    asm volatile("cp.async.cg.shared.global [%0], [%1], 16;" :: "r"(sa), "l"(gptr));
}
__device__ __forceinline__ void mma_f16(float* d, const uint32_t* a, const uint32_t* b) {
    asm volatile(
        "mma.sync.aligned.m16n8k16.row.col.f32.f16.f16.f32 "
        "{%0,%1,%2,%3}, {%4,%5,%6,%7}, {%8,%9}, {%0,%1,%2,%3};"
        : "+f"(d[0]), "+f"(d[1]), "+f"(d[2]), "+f"(d[3])
        : "r"(a[0]), "r"(a[1]), "r"(a[2]), "r"(a[3]), "r"(b[0]), "r"(b[1]));
}
__device__ __forceinline__ void ldsm_x4(uint32_t& r0, uint32_t& r1,
                                        uint32_t& r2, uint32_t& r3, uint32_t addr) {
    asm volatile("ldmatrix.sync.aligned.m8n8.x4.shared.b16 {%0,%1,%2,%3}, [%4];"
                 : "=r"(r0), "=r"(r1), "=r"(r2), "=r"(r3) : "r"(addr));
}

// ---------------------------------------------------------------------------
// float -> half converters
// ---------------------------------------------------------------------------
__device__ __forceinline__ void f2h4(const float4* s, uint2* d, int i) {
    float4 v = s[i];
    __half2 h0 = __floats2half2_rn(v.x, v.y);
    __half2 h1 = __floats2half2_rn(v.z, v.w);
    d[i] = make_uint2(*(uint32_t*)&h0, *(uint32_t*)&h1);
}
__global__ void f2h_kernel(const float4* __restrict__ src, uint2* __restrict__ dst, int n4)
{
    int i = blockIdx.x * blockDim.x + threadIdx.x;
    if (i < n4) f2h4(src, dst, i);
}
__global__ void f2h3_kernel(const float4* s0, uint2* d0, int n0,
                            const float4* s1, uint2* d1, int n1,
                            const float4* s2, uint2* d2, int n2)
{
    int i = blockIdx.x * blockDim.x + threadIdx.x;
    int stride = gridDim.x * blockDim.x;
    for (int j = i; j < n0; j += stride) f2h4(s0, d0, j);
    for (int j = i; j < n1; j += stride) f2h4(s1, d1, j);
    for (int j = i; j < n2; j += stride) f2h4(s2, d2, j);
}

// ---------------------------------------------------------------------------
// fp16 tensor-core GEMM: C[m][n] = sum_k A[m*lda+k]*B[n*ldb+k], f32 accum.
// CTA 128x128, BK=64, 8 warps (64x32), cp.async double-buffered, 2 CTAs/SM.
// SPLITK: gridDim.z splits K; each z writes its own slab C + z*M*ldc.
// M%128==0, K%(64*gridDim.z)==0; N tail allowed (zero-filled B rows).
// ---------------------------------------------------------------------------
#define LDH 72   // 64 + 8 pad (halves per smem row)

template<bool SOFTPLUS, bool SPLITK>
__global__ void __launch_bounds__(256, 2) gemm_h(
    const __half* __restrict__ A, const __half* __restrict__ B,
    const float* __restrict__ bias, float* __restrict__ C,
    int M, int N, int K, int lda, int ldb, int ldc)
{
    extern __shared__ __half sm[];
    __half (*As)[128][LDH] = (__half(*)[128][LDH])sm;
    __half (*Bs)[128][LDH] = (__half(*)[128][LDH])(sm + 2 * 128 * LDH);

    const int tid  = threadIdx.x;
    const int wid  = tid >> 5, lane = tid & 31;
    const int g    = lane >> 2, tg = lane & 3;
    const int wm   = (wid >> 2) * 64;
    const int wn   = (wid & 3) * 32;
    const int m0   = blockIdx.y * 128, n0 = blockIdx.x * 128;

    int kt0 = 0, KT = K / 64;
    if (SPLITK) {
        KT = K / 64 / gridDim.z;
        kt0 = blockIdx.z * KT;
        C += (size_t)blockIdx.z * M * ldc;
    }

    const int lm_row = (lane & 7) + ((lane >> 3) & 1) * 8;
    const int lm_col = (lane >> 4) * 8;
    const uint32_t lm_off = (uint32_t)(lm_row * LDH + lm_col) * 2;
    const uint32_t as_base = (uint32_t)__cvta_generic_to_shared(&As[0][0][0]);
    const uint32_t bs_base = (uint32_t)__cvta_generic_to_shared(&Bs[0][0][0]);
    const uint32_t tile_bytes = 128 * LDH * 2;

    if (n0 + 128 > N) {
        int rstart = N - n0; if (rstart < 0) rstart = 0;
        for (int i = tid; i < 2 * 128 * (LDH / 2); i += 256) {
            int r = (i / (LDH / 2)) & 127;
            if (r >= rstart) ((uint32_t*)&Bs[0][0][0])[i] = 0u;
        }
        __syncthreads();
    }

    auto load_tiles = [&](int kt, int buf) {
        const __half* Ab = A + (size_t)m0 * lda + (kt0 + kt) * 64;
        const __half* Bb = B + (size_t)n0 * ldb + (kt0 + kt) * 64;
#pragma unroll
        for (int i = 0; i < 4; ++i) {
            int f = tid + i * 256;
            int r = f >> 3, c = (f & 7) * 8;
            cpasync16(&As[buf][r][c], Ab + (size_t)r * lda + c);
            if (n0 + r < N)
                cpasync16(&Bs[buf][r][c], Bb + (size_t)r * ldb + c);
        }
    };

    float acc[4][4][4];
#pragma unroll
    for (int i = 0; i < 4; ++i)
#pragma unroll
        for (int j = 0; j < 4; ++j)
#pragma unroll
            for (int r = 0; r < 4; ++r) acc[i][j][r] = 0.f;

    load_tiles(0, 0);
    asm volatile("cp.async.commit_group;");

    for (int kt = 0; kt < KT; ++kt) {
        if (kt + 1 < KT) {
            load_tiles(kt + 1, (kt + 1) & 1);
            asm volatile("cp.async.commit_group;");
            asm volatile("cp.async.wait_group 1;");
        } else {
            asm volatile("cp.async.wait_group 0;");
        }
        __syncthreads();

        const int buf = kt & 1;
        const uint32_t abuf = as_base + buf * tile_bytes + lm_off;
        const uint32_t bbuf = bs_base + buf * tile_bytes + lm_off;
#pragma unroll
        for (int ks = 0; ks < 4; ++ks) {
            const uint32_t k0b = (uint32_t)(ks * 16) * 2;
            uint32_t af[4][4], bf[4][2];
#pragma unroll
            for (int mi = 0; mi < 4; ++mi)
                ldsm_x4(af[mi][0], af[mi][1], af[mi][2], af[mi][3],
                        abuf + (uint32_t)((wm + mi * 16) * LDH) * 2 + k0b);
#pragma unroll
            for (int p = 0; p < 2; ++p)
                ldsm_x4(bf[2 * p][0], bf[2 * p + 1][0], bf[2 * p][1], bf[2 * p + 1][1],
                        bbuf + (uint32_t)((wn + p * 16) * LDH) * 2 + k0b);
#pragma unroll
            for (int mi = 0; mi < 4; ++mi)
#pragma unroll
                for (int ni = 0; ni < 4; ++ni)
                    mma_f16(acc[mi][ni], af[mi], bf[ni]);
        }
        __syncthreads();
    }

    // epilogue
#pragma unroll
    for (int mi = 0; mi < 4; ++mi) {
        const int r0 = m0 + wm + mi * 16 + g;
#pragma unroll
        for (int ni = 0; ni < 4; ++ni) {
            const int col = n0 + wn + ni * 8 + 2 * tg;
            if (col >= N) continue;
            float v0 = acc[mi][ni][0], v1 = acc[mi][ni][1];
            float v2 = acc[mi][ni][2], v3 = acc[mi][ni][3];
            if (SOFTPLUS) {
                float b0 = bias[col], b1 = bias[col + 1];
                v0 += b0; v1 += b1; v2 += b0; v3 += b1;
                v0 = (v0 > 20.f) ? v0 : log1pf(expf(v0));
                v1 = (v1 > 20.f) ? v1 : log1pf(expf(v1));
                v2 = (v2 > 20.f) ? v2 : log1pf(expf(v2));
                v3 = (v3 > 20.f) ? v3 : log1pf(expf(v3));
            }
            *(float2*)&C[(size_t)r0 * ldc + col]       = make_float2(v0, v1);
            *(float2*)&C[(size_t)(r0 + 8) * ldc + col] = make_float2(v2, v3);
        }
    }
}

// ---------------------------------------------------------------------------
// split-K slab reduction: dstf[i] = sum_s part[s*slab + i]; optional half copy
// ---------------------------------------------------------------------------
template<int S, bool HALF>
__global__ void reduce_k(const float* __restrict__ part, float* __restrict__ dstf,
                         __half* __restrict__ dsth, int n)
{
    int i = blockIdx.x * blockDim.x + threadIdx.x;
    if (i >= n) return;
    float s = 0.f;
#pragma unroll
    for (int k = 0; k < S; ++k) s += part[(size_t)k * n + i];
    dstf[i] = s;
    if (HALF) dsth[i] = __float2half_rn(s);
}

// ---------------------------------------------------------------------------
// Depthwise causal conv (4-tap) + SiLU -> float (scan) + half (GEMM)
// ---------------------------------------------------------------------------
__global__ void conv_silu_kernel(const float* __restrict__ cw,
                                 const float* __restrict__ cb)
{
    int idx = blockIdx.x * blockDim.x + threadIdx.x;
    if (idx >= L_SEQ * DI) return;
    int l = idx / DI, d = idx % DI;
    float acc = cb[d];
#pragma unroll
    for (int t = 0; t < 4; ++t) {
        int ll = l - 3 + t;
        if (ll >= 0) acc = fmaf(cw[d * 4 + t], g_xz[(size_t)ll * (2 * DI) + d], acc);
    }
    float s = acc / (1.f + __expf(-acc));
    g_xs[idx]  = s;
    g_xsh[idx] = __float2half_rn(s);
}

// ---------------------------------------------------------------------------
// Chunked selective scan (3 passes)
// ---------------------------------------------------------------------------
#define PF 8
__global__ void __launch_bounds__(256) scan_part1(const float* __restrict__ A_log)
{
    const int d = blockIdx.x * 16 + (threadIdx.x >> 4);
    const int n = threadIdx.x & 15;
    const int c = blockIdx.y;
    const float a = -__expf(A_log[d * DS + n]);
    const int lbase = c * CL;

    float cdt[PF], cxv[PF], cb[PF];
#pragma unroll
    for (int j = 0; j < PF; ++j) {
        int l = lbase + j;
        cdt[j] = g_dt[(size_t)l * DI + d];
        cxv[j] = g_xs[(size_t)l * DI + d];
        cb[j]  = g_xdbl[l * XDBL + DTR + n];
    }

    float h = 0.f, P = 1.f;
    for (int l0 = 0; l0 < CL; l0 += PF) {
        float ndt[PF], nxv[PF], nb[PF];
        const bool more = (l0 + PF < CL);
        if (more) {
#pragma unroll
            for (int j = 0; j < PF; ++j) {
                int l = lbase + l0 + PF + j;
                ndt[j] = g_dt[(size_t)l * DI + d];
                nxv[j] = g_xs[(size_t)l * DI + d];
                nb[j]  = g_xdbl[l * XDBL + DTR + n];
            }
        }
#pragma unroll
        for (int j = 0; j < PF; ++j) {
            float dA = __expf(cdt[j] * a);
            h = fmaf(dA, h, cdt[j] * cb[j] * cxv[j]);
            P *= dA;
        }
        if (more) {
#pragma unroll
            for (int j = 0; j < PF; ++j) { cdt[j] = ndt[j]; cxv[j] = nxv[j]; cb[j] = nb[j]; }
        }
    }
    g_q[((size_t)c * DI + d) * DS + n] = h;
    g_P[((size_t)c * DI + d) * DS + n] = P;
}

__global__ void __launch_bounds__(256) scan_combine()
{
    int idx = blockIdx.x * blockDim.x + threadIdx.x;
    if (idx >= DI * DS) return;
    float hin = 0.f;
    g_hin[idx] = 0.f;
#pragma unroll
    for (int c = 0; c < NCH - 1; ++c) {
        hin = fmaf(g_P[(size_t)c * DI * DS + idx], hin, g_q[(size_t)c * DI * DS + idx]);
        g_hin[(size_t)(c + 1) * DI * DS + idx] = hin;
    }
}

__global__ void __launch_bounds__(256) scan_part2(
    const float* __restrict__ A_log, const float* __restrict__ Dp)
{
    const int d = blockIdx.x * 16 + (threadIdx.x >> 4);
    const int n = threadIdx.x & 15;
    const int c = blockIdx.y;
    const float a  = -__expf(A_log[d * DS + n]);
    const float Dd = Dp[d];
    const bool lead = (n == 0);
    const int lbase = c * CL;

    float cdt[PF], cxv[PF], cb[PF], cc[PF], cz[PF];
#pragma unroll
    for (int j = 0; j < PF; ++j) {
        int l = lbase + j;
        cdt[j] = g_dt[(size_t)l * DI + d];
        cxv[j] = g_xs[(size_t)l * DI + d];
        cb[j]  = g_xdbl[l * XDBL + DTR + n];
        cc[j]  = g_xdbl[l * XDBL + DTR + DS + n];
        cz[j]  = lead ? g_xz[(size_t)l * (2 * DI) + DI + d] : 0.f;
    }

    float h = g_hin[((size_t)c * DI + d) * DS + n];
    for (int l0 = 0; l0 < CL; l0 += PF) {
        float ndt[PF], nxv[PF], nb[PF], nc[PF], nz[PF];
        const bool more = (l0 + PF < CL);
        if (more) {
#pragma unroll
            for (int j = 0; j < PF; ++j) {
                int l = lbase + l0 + PF + j;
                ndt[j] = g_dt[(size_t)l * DI + d];
                nxv[j] = g_xs[(size_t)l * DI + d];
                nb[j]  = g_xdbl[l * XDBL + DTR + n];
                nc[j]  = g_xdbl[l * XDBL + DTR + DS + n];
                nz[j]  = lead ? g_xz[(size_t)l * (2 * DI) + DI + d] : 0.f;
            }
        }
#pragma unroll
        for (int j = 0; j < PF; ++j) {
            float dt = cdt[j], xv = cxv[j];
            float dA = __expf(dt * a);
            h = fmaf(dA, h, dt * cb[j] * xv);
            float p = h * cc[j];
            p += __shfl_xor_sync(0xffffffffu, p, 1);
            p += __shfl_xor_sync(0xffffffffu, p, 2);
            p += __shfl_xor_sync(0xffffffffu, p, 4);
            p += __shfl_xor_sync(0xffffffffu, p, 8);
            if (lead) {
                float z  = cz[j];
                float sz = z / (1.f + __expf(-z));
                g_yh[(size_t)(lbase + l0 + j) * DI + d] =
                    __float2half_rn((p + xv * Dd) * sz);
            }
        }
        if (more) {
#pragma unroll
            for (int j = 0; j < PF; ++j) {
                cdt[j] = ndt[j]; cxv[j] = nxv[j];
                cb[j] = nb[j]; cc[j] = nc[j]; cz[j] = nz[j];
            }
        }
    }
}

// ---------------------------------------------------------------------------
extern "C" void kernel_launch(void* const* d_in, const int* in_sizes, int n_in,
                              void* d_out, int out_size)
{
    const float* x     = (const float*)d_in[0];
    const float* W_in  = (const float*)d_in[1];
    const float* cw    = (const float*)d_in[2];
    const float* cb    = (const float*)d_in[3];
    const float* W_x   = (const float*)d_in[4];
    const float* W_dt  = (const float*)d_in[5];
    const float* b_dt  = (const float*)d_in[6];
    const float* A_log = (const float*)d_in[7];
    const float* Dp    = (const float*)d_in[8];
    const float* W_out = (const float*)d_in[9];
    float* out = (float*)d_out;

    float *xz, *xdbl, *dt, *pxdbl, *pout;
    __half *xh, *Winh, *Wxh, *Wdth, *Wouth, *xsh, *xdblh, *yh;
    cudaGetSymbolAddress((void**)&xz,    g_xz);
    cudaGetSymbolAddress((void**)&xdbl,  g_xdbl);
    cudaGetSymbolAddress((void**)&dt,    g_dt);
    cudaGetSymbolAddress((void**)&pxdbl, g_part_xdbl);
    cudaGetSymbolAddress((void**)&pout,  g_part_out);
    cudaGetSymbolAddress((void**)&xh,    g_xh);
    cudaGetSymbolAddress((void**)&Winh,  g_Winh);
    cudaGetSymbolAddress((void**)&Wxh,   g_Wxh);
    cudaGetSymbolAddress((void**)&Wdth,  g_Wdth);
    cudaGetSymbolAddress((void**)&Wouth, g_Wouth);
    cudaGetSymbolAddress((void**)&xsh,   g_xsh);
    cudaGetSymbolAddress((void**)&xdblh, g_xdblh);
    cudaGetSymbolAddress((void**)&yh,    g_yh);

    const int GSM = 4 * 128 * LDH * 2;   // 73728 B
    cudaFuncSetAttribute(gemm_h<false, false>,
        cudaFuncAttributeMaxDynamicSharedMemorySize, GSM);
    cudaFuncSetAttribute(gemm_h<true, false>,
        cudaFuncAttributeMaxDynamicSharedMemorySize, GSM);
    cudaFuncSetAttribute(gemm_h<false, true>,
        cudaFuncAttributeMaxDynamicSharedMemorySize, GSM);

    // 0) f2h (3 launches; keeps in-proj at profiler capture slot)
    const int CT = 256;
    f2h_kernel<<<(L_SEQ * DM / 4 + CT - 1) / CT, CT>>>((const float4*)x, (uint2*)xh, L_SEQ * DM / 4);
    f2h_kernel<<<(2 * DI * DM / 4 + CT - 1) / CT, CT>>>((const float4*)W_in, (uint2*)Winh, 2 * DI * DM / 4);
    f2h3_kernel<<<592, CT>>>((const float4*)W_x, (uint2*)Wxh, XDBL * DI / 4,
                             (const float4*)W_dt, (uint2*)Wdth, DI * DTR / 4,
                             (const float4*)W_out, (uint2*)Wouth, DM * DI / 4);

    // 1) xz = x @ W_in^T : grid 32x16, 2 CTAs/SM
    gemm_h<false, false><<<dim3(32, 16), 256, GSM>>>(
        xh, Winh, nullptr, xz, L_SEQ, 2 * DI, DM, DM, DM, 2 * DI);

    // 2) conv + silu
    conv_silu_kernel<<<(L_SEQ * DI + 255) / 256, 256>>>(cw, cb);

    // 3) x_dbl = xs @ W_x^T : split-K x8 (K 2048 -> 256 each), then reduce
    gemm_h<false, true><<<dim3(1, 16, 8), 256, GSM>>>(
        xsh, Wxh, nullptr, pxdbl, L_SEQ, XDBL, DI, DI, DI, XDBL);
    reduce_k<8, true><<<(L_SEQ * XDBL + 255) / 256, 256>>>(
        pxdbl, xdbl, xdblh, L_SEQ * XDBL);

    // 4) dt = softplus(x_dbl[:, :64] @ W_dt^T + b_dt) : K=64, grid 16x16
    gemm_h<true, false><<<dim3(16, 16), 256, GSM>>>(
        xdblh, Wdth, b_dt, dt, L_SEQ, DI, DTR, XDBL, DTR, DI);

    // 5) chunked selective scan
    scan_part1<<<dim3(DI / 16, NCH - 1), 256>>>(A_log);
    scan_combine<<<(DI * DS + 255) / 256, 256>>>();
    scan_part2<<<dim3(DI / 16, NCH), 256>>>(A_log, Dp);

    // 6) out = y @ W_out^T : split-K x2 (K 2048 -> 1024 each), then reduce
    gemm_h<false, true><<<dim3(8, 16, 2), 256, GSM>>>(
        yh, Wouth, nullptr, pout, L_SEQ, DM, DI, DI, DI, DM);
    reduce_k<2, false><<<(L_SEQ * DM + 255) / 256, 256>>>(
        pout, out, nullptr, L_SEQ * DM);
}